// round 12
// baseline (speedup 1.0000x reference)
#include <cuda_runtime.h>

// DTW loss: B=16, C=8, T=512 -> 128 independent 512x512 DTW DPs.
// One block (128 threads / 4 warps) per pair; lane l owns 4 DP columns.
// R12: superstep = 8 rows x 4 cols (was 4x4). sigma = lane + 35*warp (ss).
//   Taller tiles: per-superstep serialization (8 shfls, group check, loop)
//   amortized over 8 rows; block ILP plateau widens to 4.
// Handoff slot = 8 floats (2 x float4; each 16B half carries its own
//   sentinel in .w -- no cross-half write-ordering assumed). Slot lag =
//   IWS-31 = 4 -> 4-slot BIG guard prefix per region. Group = 2 ss; one
//   combined sentinel check per group (cold: producer leads by 3-4 ss).
// BIG-fill: fill carries are bit-exact BIG (1e30 + c == 1e30 in fp32),
//   warp0 polls frozen BIG slots, drain garbage finite/>=0, never consumed
//   by in-window computations (boundary equalities exact).

#define TT    512
#define RPS   8                      // rows per superstep
#define IWS   35
#define SIGMX (31 + 3 * IWS)         // 136
#define NSS   (TT / RPS + SIGMX)     // 200 supersteps
#define NG    (NSS / 2)              // 100 groups of 2 ss
#define LAG   (IWS - 31)             // 4 (consumer reads slot t-LAG)
#define REG4  (2 * (LAG + NSS))      // float4 per region = 408
#define BIGF  1e30f

__device__ float        g_partials[128];
__device__ unsigned int g_counter = 0;

// One DP row: 4 cells. up0..3 = dtw[i-1][j0..j3], lprev = dtw[i-1][j0-1],
// L_ = dtw[i][j0-1]. Updates ups, lprev; writes row carry (col j3) to cO_.
#define ROW(xi_, L_, cO_) do {                                           \
    float m;                                                             \
    m = fminf(up0, lprev); const float t0 = fabsf((xi_) - y0) + fminf((L_), m); \
    m = fminf(up1, up0 );  const float t1 = fabsf((xi_) - y1) + fminf(t0, m);   \
    m = fminf(up2, up1 );  const float t2 = fabsf((xi_) - y2) + fminf(t1, m);   \
    m = fminf(up3, up2 );  const float t3 = fabsf((xi_) - y3) + fminf(t2, m);   \
    up0 = t0; up1 = t1; up2 = t2; up3 = t3; lprev = (L_); cO_ = t3;      \
} while (0)

// One superstep: 8 rows. xA_/xB_ = 8 x-values, hA_/hB_ = 8 cross-warp lefts.
#define SS8(xA_, xB_, hA_, hB_, k_) do {                                 \
    float L0 = __shfl_up_sync(0xffffffffu, c0, 1);                       \
    float L1 = __shfl_up_sync(0xffffffffu, c1, 1);                       \
    float L2 = __shfl_up_sync(0xffffffffu, c2, 1);                       \
    float L3 = __shfl_up_sync(0xffffffffu, c3, 1);                       \
    float L4 = __shfl_up_sync(0xffffffffu, c4, 1);                       \
    float L5 = __shfl_up_sync(0xffffffffu, c5, 1);                       \
    float L6 = __shfl_up_sync(0xffffffffu, c6, 1);                       \
    float L7 = __shfl_up_sync(0xffffffffu, c7, 1);                       \
    if (lane == 0) { L0 = hA_.x; L1 = hA_.y; L2 = hA_.z; L3 = hA_.w;     \
                     L4 = hB_.x; L5 = hB_.y; L6 = hB_.z; L7 = hB_.w; }   \
    ROW(xA_.x, L0, c0); ROW(xA_.y, L1, c1);                              \
    ROW(xA_.z, L2, c2); ROW(xA_.w, L3, c3);                              \
    ROW(xB_.x, L4, c4); ROW(xB_.y, L5, c5);                              \
    ROW(xB_.z, L6, c6); ROW(xB_.w, L7, c7);                              \
    if (prod) { qq[k_]     = make_float4(c0, c1, c2, c3);                \
                qq[k_ + 1] = make_float4(c4, c5, c6, c7); }              \
} while (0)

// Cold path: volatile re-poll one 16B half until its .w leaves sentinel.
#define FIXSLOT(h_, k_) do {                                             \
    volatile float* vp = (volatile float*)(pp + (k_));                   \
    float w = vp[3];                                                     \
    while (w < 0.0f) { w = vp[3]; }                                      \
    (h_).x = vp[0]; (h_).y = vp[1]; (h_).z = vp[2]; (h_).w = w;          \
} while (0)

__global__ __launch_bounds__(128, 1)
void dtw_fused_kernel(const float* __restrict__ inputs,
                      const float* __restrict__ targets,
                      float* __restrict__ out) {
    const int p    = blockIdx.x;
    const float* x = inputs + p * TT;
    const int tid  = threadIdx.x;
    const int lane = tid & 31;
    const int warp = tid >> 5;
    const int sig  = lane + IWS * warp;

    // x rows: 2 float4 per superstep, zero-padded SIGMX ss on both sides.
    __shared__ float4 xsbuf[2 * (SIGMX + TT / RPS + SIGMX) + 2];  // 674
    // handbuf: 8 frozen BIG float4 (warp0) + 3 regions of REG4 float4.
    __shared__ float4 handbuf[8 + 3 * REG4];                      // 1232

    {   // init smem
        float* xf = (float*)xsbuf;
        const int PRE   = SIGMX * RPS;                    // 1088 floats
        const int TOTXF = (2 * (SIGMX + TT / RPS + SIGMX) + 2) * 4;
        for (int k = tid; k < PRE; k += 128)              xf[k] = 0.0f;
        for (int k = PRE + TT + tid; k < TOTXF; k += 128) xf[k] = 0.0f;
        for (int k = tid; k < TT; k += 128)               xf[PRE + k] = x[k];
        float* hf = (float*)handbuf;
        for (int k = tid; k < (8 + 3 * REG4) * 4; k += 128) hf[k] = -1.0f;
    }
    __syncthreads();
    {   // overwrite guards with BIG: warp0 block + each region's LAG slots
        float* hf = (float*)handbuf;
        for (int k = tid; k < 32; k += 128) hf[k] = BIGF;             // warp0
        for (int r = 0; r < 3; ++r)
            for (int k = tid; k < LAG * 2 * 4; k += 128)
                hf[(8 + r * REG4) * 4 + k] = BIGF;
    }

    const float4 yq = ((const float4*)(targets + p * TT))[tid];
    const float y0 = yq.x, y1 = yq.y, y2 = yq.z, y3 = yq.w;

    float up0 = BIGF, up1 = BIGF, up2 = BIGF, up3 = BIGF;
    float lprev = (tid == 0) ? 0.0f : BIGF;
    float c0 = BIGF, c1 = BIGF, c2 = BIGF, c3 = BIGF;
    float c4 = BIGF, c5 = BIGF, c6 = BIGF, c7 = BIGF;

    const bool prod = (lane == 31 && warp < 3);
    // consumer: region base = logical slot -LAG; ss t reads float4 2t,2t+1.
    float4* pp = (warp > 0) ? (handbuf + 8 + (warp - 1) * REG4) : handbuf;
    const int pinc = (warp > 0) ? 4 : 0;       // warp0 re-reads its BIG block
    float4* qq = handbuf + 8 + warp * REG4 + 2 * LAG;   // producer ss-0 slot
    const float4* xp = xsbuf + 2 * (SIGMX - sig);

    __syncthreads();

    for (int g = 0; g < NG; ++g) {
        // This group's 4 handoff float4 (2 slots), broadcast LDS.128.
        float4 ha0 = pp[0], ha1 = pp[1], hb0 = pp[2], hb1 = pp[3];
        // One combined, warp-uniform sentinel check per group (cold).
        if ((ha0.w < 0.0f) | (ha1.w < 0.0f) | (hb0.w < 0.0f) | (hb1.w < 0.0f)) {
            FIXSLOT(ha0, 0); FIXSLOT(ha1, 1); FIXSLOT(hb0, 2); FIXSLOT(hb1, 3);
        }

        const float4 xa0 = xp[0], xa1 = xp[1], xb0 = xp[2], xb1 = xp[3];

        SS8(xa0, xa1, ha0, ha1, 0);
        SS8(xb0, xb1, hb0, hb1, 2);

        pp += pinc; qq += 4; xp += 4;
    }

    // tid 127 (sig = 136): last valid ss = 199; c7 = dtw[512][512].
    if (tid == 127) {
        g_partials[p] = c7 * (1.0f / (float)TT);
        __threadfence();
        unsigned int old = atomicAdd(&g_counter, 1u);
        if (old == 127u) {
            volatile float* gp = g_partials;
            float sum = 0.0f;
            #pragma unroll 16
            for (int k = 0; k < 128; ++k) sum += gp[k];
            out[0] = sum * 0.125f;                       // (1/C) * sum_b
            *(volatile unsigned int*)&g_counter = 0;     // reset for replay
        }
    }
}

extern "C" void kernel_launch(void* const* d_in, const int* in_sizes, int n_in,
                              void* d_out, int out_size) {
    const float* inputs  = (const float*)d_in[0];
    const float* targets = (const float*)d_in[1];
    float* out = (float*)d_out;
    (void)in_sizes; (void)n_in; (void)out_size;

    dtw_fused_kernel<<<128, 128>>>(inputs, targets, out);
}

// round 13
// speedup vs baseline: 1.4281x; 1.4281x over previous
#include <cuda_runtime.h>

// DTW loss: B=16, C=8, T=512 -> 128 independent 512x512 DTW DPs.
// One block (128 threads / 4 warps) per pair; lane l owns 4 DP columns.
// Superstep = 4 rows x 4 cols; sigma = lane + 39*warp; groups of 4 ss with
// one combined sentinel check (R11 structure, best so far).
// R13: SHFLs interleaved into the row stream. shfl(c_r) issues right after
//   row r produces c_r, yielding NEXT-superstep L values ~3 rows early ->
//   SHFL latency (26cy) fully overlapped; cross-ss recurrence = up-register
//   chain only. Handoff slot index shifts +1 (L's prepared for ss t+1 read
//   slot t-7); 8-slot BIG guard prefix covers it (boundaries re-verified:
//   first consumed slot = producer's first valid publish, last = its last).
// BIG-fill handoff: fill carries bit-exact BIG (1e30+c==1e30), warp0 polls
//   frozen BIG slots, drain garbage >= 0 and never consumed in-window.

#define TT    512
#define IWS   39
#define SIGMX (31 + 3 * IWS)       // 148
#define NSS   (TT / 4 + SIGMX)     // 276 supersteps
#define NG    (NSS / 4)            // 69 groups
#define GUARD 8
#define REG   (GUARD + NSS)
#define BIGF  1e30f

__device__ float        g_partials[128];
__device__ unsigned int g_counter = 0;

// One DP row: 4 cells. up0..3 = dtw[i-1][j0..j3], lprev = dtw[i-1][j0-1],
// L_ = dtw[i][j0-1]. Updates ups, lprev; leaves row carry in cO_.
#define ROW(xi_, L_, cO_) do {                                                 \
    float m;                                                                   \
    m = fminf(up0, lprev); const float t0 = fabsf((xi_) - y0) + fminf((L_), m);\
    m = fminf(up1, up0 );  const float t1 = fabsf((xi_) - y1) + fminf(t0, m);  \
    m = fminf(up2, up1 );  const float t2 = fabsf((xi_) - y2) + fminf(t1, m);  \
    m = fminf(up3, up2 );  const float t3 = fabsf((xi_) - y3) + fminf(t2, m);  \
    up0 = t0; up1 = t1; up2 = t2; up3 = t3; lprev = (L_); cO_ = t3;            \
} while (0)

// One superstep with interleaved shfls. Consumes L0..L3 (this ss), produces
// L0..L3 for the NEXT ss (shfl right after each carry; lane0 <- hq_ = next
// ss's cross-warp slot).
#define SSP(xq_, hq_, k_) do {                                                 \
    ROW(xq_.x, L0, c0);                                                        \
    float n0 = __shfl_up_sync(0xffffffffu, c0, 1);                             \
    ROW(xq_.y, L1, c1);                                                        \
    float n1 = __shfl_up_sync(0xffffffffu, c1, 1);                             \
    ROW(xq_.z, L2, c2);                                                        \
    float n2 = __shfl_up_sync(0xffffffffu, c2, 1);                             \
    ROW(xq_.w, L3, c3);                                                        \
    float n3 = __shfl_up_sync(0xffffffffu, c3, 1);                             \
    if (lane == 0) { n0 = hq_.x; n1 = hq_.y; n2 = hq_.z; n3 = hq_.w; }         \
    if (prod) qq[k_] = make_float4(c0, c1, c2, c3);                            \
    L0 = n0; L1 = n1; L2 = n2; L3 = n3;                                        \
} while (0)

// Cold path: volatile re-poll of one slot until its .w leaves sentinel.
#define FIXSLOT(h_, k_) do {                                                   \
    volatile float* vp = (volatile float*)(pp + (k_));                         \
    float w = vp[3];                                                           \
    while (w < 0.0f) { w = vp[3]; }                                            \
    (h_).x = vp[0]; (h_).y = vp[1]; (h_).z = vp[2]; (h_).w = w;                \
} while (0)

__global__ __launch_bounds__(128, 1)
void dtw_fused_kernel(const float* __restrict__ inputs,
                      const float* __restrict__ targets,
                      float* __restrict__ out) {
    const int p    = blockIdx.x;
    const float* x = inputs + p * TT;
    const int tid  = threadIdx.x;
    const int lane = tid & 31;
    const int warp = tid >> 5;
    const int sig  = lane + IWS * warp;

    __shared__ float4 xsbuf[SIGMX + TT / 4 + SIGMX];      // 424 float4
    __shared__ float4 handbuf[4 + 3 * REG];               // 856 float4

    {   // init smem
        float* xf = (float*)xsbuf;
        const int PRE = SIGMX * 4;
        for (int k = tid; k < PRE; k += 128) xf[k] = 0.0f;
        for (int k = tid; k < PRE; k += 128) xf[PRE + TT + k] = 0.0f;
        for (int k = tid; k < TT;  k += 128) xf[PRE + k] = x[k];
        float* hf = (float*)handbuf;
        for (int k = tid; k < (4 + 3 * REG) * 4; k += 128) hf[k] = -1.0f;
    }
    __syncthreads();
    {   // guards -> BIG (warp0 block + each region's 8-slot prefix)
        float* hf = (float*)handbuf;
        for (int k = tid; k < 16; k += 128) hf[k] = BIGF;
        for (int r = 0; r < 3; ++r)
            for (int k = tid; k < GUARD * 4; k += 128)
                hf[(4 + r * REG) * 4 + k] = BIGF;
    }

    const float4 yq = ((const float4*)(targets + p * TT))[tid];
    const float y0 = yq.x, y1 = yq.y, y2 = yq.z, y3 = yq.w;

    float up0 = BIGF, up1 = BIGF, up2 = BIGF, up3 = BIGF;
    float lprev = (tid == 0) ? 0.0f : BIGF;
    float c0 = BIGF, c1 = BIGF, c2 = BIGF, c3 = BIGF;
    float L0 = BIGF, L1 = BIGF, L2 = BIGF, L3 = BIGF;   // lefts for ss 0

    const bool prod = (lane == 31 && warp < 3);
    // Consumer base: region start (logical slot -8) SHIFTED +1 because L's
    // made at ss t feed ss t+1 (slot t+1-8 = t-7). Group g loads pp[0..3] =
    // logical slots 4g-7 .. 4g-4. warp0 stays frozen on its BIG block.
    float4* pp = (warp > 0) ? (handbuf + 4 + (warp - 1) * REG + 1) : handbuf;
    const int pinc = (warp > 0) ? 4 : 0;
    float4* qq = handbuf + 4 + warp * REG + GUARD;        // producer slot 0
    const float4* xp = xsbuf + SIGMX - sig;

    __syncthreads();

    for (int g = 0; g < NG; ++g) {
        // Next-ss handoff slots for the 4 supersteps of this group.
        float4 hq0 = pp[0], hq1 = pp[1], hq2 = pp[2], hq3 = pp[3];
        if ((hq0.w < 0.0f) | (hq1.w < 0.0f) | (hq2.w < 0.0f) | (hq3.w < 0.0f)) {
            FIXSLOT(hq0, 0); FIXSLOT(hq1, 1); FIXSLOT(hq2, 2); FIXSLOT(hq3, 3);
        }

        const float4 xq0 = xp[0], xq1 = xp[1], xq2 = xp[2], xq3 = xp[3];

        SSP(xq0, hq0, 0);
        SSP(xq1, hq1, 1);
        SSP(xq2, hq2, 2);
        SSP(xq3, hq3, 3);

        pp += pinc; qq += 4; xp += 4;
    }

    // tid 127 (sig = 148): last valid ss = 275; c3 = dtw[512][512].
    if (tid == 127) {
        g_partials[p] = c3 * (1.0f / (float)TT);
        __threadfence();
        unsigned int old = atomicAdd(&g_counter, 1u);
        if (old == 127u) {
            volatile float* gp = g_partials;
            float sum = 0.0f;
            #pragma unroll 16
            for (int k = 0; k < 128; ++k) sum += gp[k];
            out[0] = sum * 0.125f;                       // (1/C) * sum_b
            *(volatile unsigned int*)&g_counter = 0;     // reset for replay
        }
    }
}

extern "C" void kernel_launch(void* const* d_in, const int* in_sizes, int n_in,
                              void* d_out, int out_size) {
    const float* inputs  = (const float*)d_in[0];
    const float* targets = (const float*)d_in[1];
    float* out = (float*)d_out;
    (void)in_sizes; (void)n_in; (void)out_size;

    dtw_fused_kernel<<<128, 128>>>(inputs, targets, out);
}